// round 16
// baseline (speedup 1.0000x reference)
#include <cuda_runtime.h>
#include <cstdint>
#include <cstddef>

// ---------------- problem constants ----------------
#define FF   128
#define EE   128
#define VV   4
#define BB   2
#define NHh  7
#define PFp  32768
#define P5p  8192
#define P4p  2048
#define N6n  196608
#define N5n  49152
#define N4n  12288
#define SA   132            // slice stride (words): conflict-free mma A reads
#define SLW  (16 * SA)      // 2112 words per warp slice
#define WTW  576            // wtab words per pc4: 16 o16 x 9 float4-slots... (floats)
#define NT   512

typedef unsigned long long u64;

__device__ __forceinline__ unsigned f2tf32(float x) {
    unsigned y;
    asm("cvt.rna.tf32.f32 %0, %1;" : "=r"(y) : "f"(x));
    return y;
}

__device__ __forceinline__ u64 fma2(u64 a, u64 b, u64 c) {
    u64 d;
    asm("fma.rn.f32x2 %0, %1, %2, %3;" : "=l"(d) : "l"(a), "l"(b), "l"(c));
    return d;
}
__device__ __forceinline__ u64 add2(u64 a, u64 b) {
    u64 d;
    asm("add.rn.f32x2 %0, %1, %2;" : "=l"(d) : "l"(a), "l"(b));
    return d;
}

__device__ __forceinline__ void mma_tf32(float c[4],
                                         unsigned a0, unsigned a1, unsigned a2, unsigned a3,
                                         unsigned b0, unsigned b1) {
    asm volatile(
        "mma.sync.aligned.m16n8k8.row.col.f32.tf32.tf32.f32 "
        "{%0,%1,%2,%3}, {%4,%5,%6,%7}, {%8,%9}, {%0,%1,%2,%3};\n"
        : "+f"(c[0]), "+f"(c[1]), "+f"(c[2]), "+f"(c[3])
        : "r"(a0), "r"(a1), "r"(a2), "r"(a3), "r"(b0), "r"(b1));
}

__device__ __forceinline__ void cp16(unsigned dst, const void* src) {
    asm volatile("cp.async.cg.shared.global [%0], [%1], 16;\n" :: "r"(dst), "l"(src) : "memory");
}

// ========== fully warp-independent fused kernel ==========
// warp = one (b, pc4, v) task: gather 16 t6 rows -> private smem slice,
// M16xN128 tf32 mma, epilogue into own slice, interp += e5+e4, write out.
// ONE __syncthreads (W-frag fill); all other sync is __syncwarp/wait_group.
__global__ __launch_bounds__(NT, 1)
void fused_kernel(const float* __restrict__ t6, const float* __restrict__ t5,
                  const float* __restrict__ t4, const float* __restrict__ W,
                  const float* __restrict__ bias,
                  const float* __restrict__ rd5, const float* __restrict__ rd4,
                  const float* __restrict__ m5,  const float* __restrict__ m4,
                  const int* __restrict__ var_idx, const int* __restrict__ idx6,
                  const int* __restrict__ nh5, const int* __restrict__ nh4,
                  float* __restrict__ out)
{
    extern __shared__ unsigned sm[];
    unsigned* sWf  = sm;                               // 16384 words: W frags
    unsigned* sSl  = sm + 16384;                       // 16 x SLW warp slices
    float*    wtab = (float*)(sm + 16384 + 16 * SLW);  // 4 pc4 x WTW floats
    float*    sB   = wtab + 4 * WTW;                   // bias [128]

    const int bx   = blockIdx.x;                       // pc4 group 0..511
    const int b    = blockIdx.y;
    const int tid  = threadIdx.x;
    const int warp = tid >> 5, lane = tid & 31;
    const int ql   = warp >> 2;                        // pc4-in-CTA 0..3
    const int v    = warp & 3;
    const int pc4  = bx * 4 + ql;
    const int tv   = var_idx[b * VV + v];

    // ---- per-warp row indices (lane<16) ----
    int gi = 0;
    if (lane < 16) gi = idx6[b * PFp + pc4 * 16 + lane];

    // ---- issue own 16-row gather immediately ----
    unsigned* slice = sSl + warp * SLW;
    {
        const float* tb = t6 + (size_t)tv * N6n * FF;
        unsigned aBase = (unsigned)__cvta_generic_to_shared(slice);
        #pragma unroll
        for (int j = 0; j < 16; j++) {
            int rowIdx = __shfl_sync(0xffffffffu, gi, j);
            cp16(aBase + (unsigned)(j * SA + lane * 4) * 4u,
                 tb + (size_t)rowIdx * FF + lane * 4);
        }
        asm volatile("cp.async.commit_group;\n" ::: "memory");
    }

    // ---- cooperative W-frag fill (the only CTA-wide shared state) ----
    for (int fi = tid; fi < 8192; fi += NT) {
        int kt = fi >> 9, nt = (fi >> 5) & 15, ln = fi & 31;
        int gg = ln >> 2, tt = ln & 3;
        int k0 = kt * 8 + tt, n = nt * 8 + gg;
        sWf[fi * 2 + 0] = f2tf32(W[(size_t)k0 * EE + n]);
        sWf[fi * 2 + 1] = f2tf32(W[(size_t)(k0 + 4) * EE + n]);
    }
    if (tid < EE) sB[tid] = bias[tid];

    // ---- per-warp neighbor indices (register-resident) ----
    int nh4r = 0, nh5r = 0;
    if (lane < 7)
        nh4r = nh4[((size_t)(b * P4p) + pc4) * NHh + lane];
    if (lane < 28)
        nh5r = nh5[((size_t)(b * P5p) + pc4 * 4 + lane / 7) * NHh + lane % 7];

    // ---- interpolation weights -> wtab (the 4 v-warps of a pc4 write
    //      identical values; benign same-value race, each warp writes the
    //      full table itself before reading it) ----
    float* wt = wtab + ql * WTW;                       // [16 o16][9 float-quads]
    {
        float w[NHh];
        const float* rdp; const float* mkp;
        if (lane < 16) {
            rdp = rd4 + ((size_t)(b * P4p + pc4) * 16 + lane) * NHh;
            mkp = m4  +  (size_t)(b * P4p + pc4) * NHh;
        } else {
            int g5 = lane - 16, s5 = g5 >> 2, o5 = g5 & 3;
            int pc5 = pc4 * 4 + s5;
            rdp = rd5 + ((size_t)(b * P5p + pc5) * 4 + o5) * NHh;
            mkp = m5  +  (size_t)(b * P5p + pc5) * NHh;
        }
        float ss = 0.f;
        #pragma unroll
        for (int n = 0; n < NHh; n++) {
            float x  = rdp[n] + mkp[n] * 1e10f;
            float wi = 1.0f / (1e-20f + x);
            w[n] = wi; ss += wi;
        }
        float inv = 1.0f / ss;
        #pragma unroll
        for (int n = 0; n < NHh; n++) w[n] *= inv;

        const int o = lane & 15;                       // o16 (e4) or g5 (e5)
        float2* dst = (float2*)(wt + o * 36) + (lane < 16 ? 0 : 1);
        #pragma unroll
        for (int n = 0; n < NHh; n++)
            dst[n * 2] = make_float2(w[n], w[n]);
    }

    // ---- prefetch e4 rows (in flight across W-sync + mma) ----
    ulonglong2 f4[NHh];
    {
        const ulonglong2* tb4 = (const ulonglong2*)(t4 + (size_t)tv * N4n * FF);
        #pragma unroll
        for (int n = 0; n < NHh; n++) {
            int idx = __shfl_sync(0xffffffffu, nh4r, n);
            f4[n] = tb4[(size_t)idx * 32 + lane];
        }
    }

    __syncthreads();                                   // sWf + sB ready (only CTA sync)
    asm volatile("cp.async.wait_group 0;\n" ::: "memory");
    __syncwarp();                                      // own slice populated

    // ---- mma: M16 x N128, warp-private ----
    const int g = lane >> 2, t = lane & 3;
    {
        const unsigned* A = slice;
        float acc[16][4];
        #pragma unroll
        for (int nt = 0; nt < 16; nt++) {
            acc[nt][0] = 0.f; acc[nt][1] = 0.f; acc[nt][2] = 0.f; acc[nt][3] = 0.f;
        }
        #pragma unroll 2
        for (int kt = 0; kt < 16; kt++) {
            const int kb = kt * 8;
            unsigned a0 = A[(g    ) * SA + kb + t];
            unsigned a1 = A[(g + 8) * SA + kb + t];
            unsigned a2 = A[(g    ) * SA + kb + t + 4];
            unsigned a3 = A[(g + 8) * SA + kb + t + 4];
            const uint2* wrow = (const uint2*)sWf + kt * 512 + lane;
            #pragma unroll
            for (int nt = 0; nt < 16; nt++) {
                uint2 bb = wrow[nt * 32];
                mma_tf32(acc[nt], a0, a1, a2, a3, bb.x, bb.y);
            }
        }

        // epilogue: +bias -> own slice (intra-warp transpose via smem)
        float* res = (float*)slice;
        #pragma unroll
        for (int nt = 0; nt < 16; nt++) {
            int col = nt * 8 + 2 * t;
            float b0 = sB[col], b1 = sB[col + 1];
            *(float2*)(res + (g    ) * SA + col) =
                make_float2(acc[nt][0] + b0, acc[nt][1] + b1);
            *(float2*)(res + (g + 8) * SA + col) =
                make_float2(acc[nt][2] + b0, acc[nt][3] + b1);
        }
    }
    __syncwarp();                                      // warp wrote full 16x128 slice

    // ---- interp: += e5 + e4, write out ----
    {
        const ulonglong2* tb5 = (const ulonglong2*)(t5 + (size_t)tv * N5n * FF);
        const float* res = (const float*)slice;
        const ulonglong2* wt2 = (const ulonglong2*)wt; // [o16*9 + n] pairs
        float* op = out + ((size_t)(b * VV + v) * PFp + pc4 * 16) * EE;

        ulonglong2 fA[NHh], fB[NHh];
        #pragma unroll
        for (int n = 0; n < NHh; n++) {
            int idx = __shfl_sync(0xffffffffu, nh5r, 0 * 7 + n);
            fA[n] = tb5[(size_t)idx * 32 + lane];
        }
        #pragma unroll
        for (int n = 0; n < NHh; n++) {
            int idx = __shfl_sync(0xffffffffu, nh5r, 1 * 7 + n);
            fB[n] = tb5[(size_t)idx * 32 + lane];
        }

        auto doS5 = [&](int s5, const ulonglong2* f5) {
            #pragma unroll
            for (int o5 = 0; o5 < 4; o5++) {
                const int o16 = s5 * 4 + o5;
                ulonglong2 a = *(const ulonglong2*)(res + o16 * SA + 4 * lane);
                u64 p0a = 0, p1a = 0;
                #pragma unroll
                for (int n = 0; n < NHh; n++) {
                    ulonglong2 wv = wt2[o16 * 9 + n];  // (w4w4, w5w5)
                    a.x = fma2(wv.x, f4[n].x, a.x);
                    a.y = fma2(wv.x, f4[n].y, a.y);
                    p0a = fma2(wv.y, f5[n].x, p0a);
                    p1a = fma2(wv.y, f5[n].y, p1a);
                }
                a.x = add2(a.x, p0a);
                a.y = add2(a.y, p1a);
                *(ulonglong2*)(op + (size_t)o16 * EE + 4 * lane) = a;
            }
        };

        doS5(0, fA);
        #pragma unroll
        for (int n = 0; n < NHh; n++) {
            int idx = __shfl_sync(0xffffffffu, nh5r, 2 * 7 + n);
            fA[n] = tb5[(size_t)idx * 32 + lane];
        }
        doS5(1, fB);
        #pragma unroll
        for (int n = 0; n < NHh; n++) {
            int idx = __shfl_sync(0xffffffffu, nh5r, 3 * 7 + n);
            fB[n] = tb5[(size_t)idx * 32 + lane];
        }
        doS5(2, fA);
        doS5(3, fB);
    }
}

// ===================== launch =====================
extern "C" void kernel_launch(void* const* d_in, const int* in_sizes, int n_in,
                              void* d_out, int out_size)
{
    const float* table6  = (const float*)d_in[0];
    const float* table5  = (const float*)d_in[1];
    const float* table4  = (const float*)d_in[2];
    const float* W       = (const float*)d_in[3];
    const float* bias    = (const float*)d_in[4];
    const float* rd5     = (const float*)d_in[5];
    const float* rd4     = (const float*)d_in[6];
    const float* m5      = (const float*)d_in[7];
    const float* m4      = (const float*)d_in[8];
    const int*   var_idx = (const int*)d_in[9];
    const int*   idx6    = (const int*)d_in[10];
    const int*   nh5     = (const int*)d_in[11];
    const int*   nh4     = (const int*)d_in[12];
    float* out = (float*)d_out;

    // 16384 (W) + 16*2112 (slices) + 4*576 (wtab) + 128 (bias)
    //   = 52,608 words = 210,432 B  (< 227 KB opt-in limit)
    const int smem = (16384 + 16 * SLW + 4 * WTW + 128) * 4;
    cudaFuncSetAttribute(fused_kernel, cudaFuncAttributeMaxDynamicSharedMemorySize, smem);

    dim3 grid(P4p / 4, BB);   // 512 x 2 = 1024 CTAs, 16 warp-tasks each
    fused_kernel<<<grid, NT, smem>>>(table6, table5, table4, W, bias,
                                     rd5, rd4, m5, m4,
                                     var_idx, idx6, nh5, nh4, out);
}